// round 1
// baseline (speedup 1.0000x reference)
#include <cuda_runtime.h>
#include <cuda_bf16.h>
#include <cstdint>

// Problem constants (TMDLayer): B=8, N=2048, F=256, L=16, EPS=0.25
#define BB 8
#define NN 2048
#define FF 256
#define LL 16
#define EPSV 0.25f

// ---------------- device scratch ----------------
__device__ float g_z[BB * NN * LL];   // projected z  [B,N,L]
__device__ float g_sq[BB * NN];       // |z|^2
__device__ float g_pi[BB * NN];       // pi(z)
__device__ float g_c[BB * NN];        // pi/q

// ---------------- helpers ----------------
__device__ __forceinline__ void cp_async16(void* dst_smem, const void* src_gmem) {
    unsigned s = (unsigned)__cvta_generic_to_shared(dst_smem);
    asm volatile("cp.async.cg.shared.global [%0], [%1], 16;\n" :: "r"(s), "l"(src_gmem));
}
__device__ __forceinline__ void cp_async_commit() {
    asm volatile("cp.async.commit_group;\n");
}
__device__ __forceinline__ void cp_async_wait_all() {
    asm volatile("cp.async.wait_group 0;\n");
}

// =====================================================================
// Kernel 1a: z = x @ proj_w^T + proj_b ; sq = |z|^2
// Block: 256 threads handles 16 points. Grid: B*N/16 = 1024.
// =====================================================================
__global__ void __launch_bounds__(256) k_proj(const float* __restrict__ x,
                                              const float* __restrict__ pw,
                                              const float* __restrict__ pb) {
    __shared__ float xs[16][260];     // padded (260*4B rows keep float4 align, kill conflicts)
    __shared__ float pws[16][257];
    __shared__ float red[16][17];

    const int tid = threadIdx.x;
    const int p0 = blockIdx.x * 16;   // flat point index (b*N+n)
    const float* xbase = x + (size_t)p0 * FF;

    // load x tile [16][256] via float4
    for (int i = tid; i < 16 * 64; i += 256) {
        int r = i >> 6, c = (i & 63) << 2;
        float4 v = *reinterpret_cast<const float4*>(xbase + r * FF + c);
        *reinterpret_cast<float4*>(&xs[r][c]) = v;
    }
    // load proj_w [16][256]
    for (int i = tid; i < LL * FF; i += 256) pws[i >> 8][i & 255] = pw[i];
    __syncthreads();

    const int n = tid >> 4;   // local point
    const int l = tid & 15;   // output feature
    float acc = pb[l];
#pragma unroll 8
    for (int f = 0; f < FF; f++) acc = fmaf(xs[n][f], pws[l][f], acc);

    g_z[(size_t)(p0 + n) * LL + l] = acc;
    red[n][l] = acc * acc;
    __syncthreads();
    if (l == 0) {
        float s = 0.f;
#pragma unroll
        for (int j = 0; j < LL; j++) s += red[n][j];
        g_sq[p0 + n] = s;
    }
}

// =====================================================================
// Kernel 1b: pi = sigmoid( relu(z @ w1^T + b1) @ w2^T + b2 )
// Block: 256 threads = 256 f-channels, handles 16 points. Grid: 1024.
// =====================================================================
__global__ void __launch_bounds__(256) k_pi(const float* __restrict__ w1,
                                            const float* __restrict__ b1,
                                            const float* __restrict__ w2,
                                            const float* __restrict__ b2) {
    __shared__ float zs[16][17];
    __shared__ float w1t[16][257];    // transposed: w1t[l][f]
    __shared__ float w2s[256];
    __shared__ float red[256][17];    // red[f][n]

    const int tid = threadIdx.x;
    const int p0 = blockIdx.x * 16;

    for (int i = tid; i < 16 * LL; i += 256) zs[i >> 4][i & 15] = g_z[(size_t)p0 * LL + i];
    for (int i = tid; i < FF * LL; i += 256) {
        int f = i >> 4, l = i & 15;
        w1t[l][f] = w1[i];
    }
    w2s[tid] = w2[tid];
    __syncthreads();

    const int f = tid;
    const float bf = b1[f];
    const float wf = w2s[f];
#pragma unroll
    for (int n = 0; n < 16; n++) {
        float h = bf;
#pragma unroll
        for (int l = 0; l < LL; l++) h = fmaf(zs[n][l], w1t[l][f], h);
        h = fmaxf(h, 0.f);
        red[f][n] = h * wf;
    }
    __syncthreads();
    // tree-reduce over 256 f
    for (int s = 128; s > 0; s >>= 1) {
        if (tid < s) {
#pragma unroll
            for (int n = 0; n < 16; n++) red[tid][n] += red[tid + s][n];
        }
        __syncthreads();
    }
    if (tid < 16) {
        float t = red[0][tid] + b2[0];
        g_pi[p0 + tid] = 1.0f / (1.0f + __expf(-t));
    }
}

// =====================================================================
// Kernel 2: q[n] = sum_m exp(-d2(n,m)) ; c = pi/q
// Block: 256 threads = 32 rows x 8 m-lanes. Grid: (N/32, B) = (64, 8).
// =====================================================================
__global__ void __launch_bounds__(256) k_q(void) {
    __shared__ float znS[32][17];
    __shared__ float sqnS[32];
    __shared__ float zmS[256][17];
    __shared__ float sqmS[256];

    const int tid = threadIdx.x;
    const int b = blockIdx.y;
    const int n0 = blockIdx.x * 32;
    const float* zb = g_z + (size_t)b * NN * LL;
    const float* sqb = g_sq + (size_t)b * NN;

    for (int i = tid; i < 32 * LL; i += 256) znS[i >> 4][i & 15] = zb[(size_t)n0 * LL + i];
    if (tid < 32) sqnS[tid] = sqb[n0 + tid];
    __syncthreads();

    const int n = tid >> 3;
    const int j = tid & 7;
    float znr[LL];
#pragma unroll
    for (int l = 0; l < LL; l++) znr[l] = znS[n][l];
    const float sqn_r = sqnS[n];
    const float kscale = 1.0f / (4.0f * EPSV);

    float qacc = 0.f;
    for (int t = 0; t < NN / 256; t++) {
        __syncthreads();
        for (int i = tid; i < 256 * LL; i += 256) zmS[i >> 4][i & 15] = zb[(size_t)(t * 256) * LL + i];
        sqmS[tid] = sqb[t * 256 + tid];
        __syncthreads();
#pragma unroll 4
        for (int mm = j; mm < 256; mm += 8) {
            float dot = 0.f;
#pragma unroll
            for (int l = 0; l < LL; l++) dot = fmaf(znr[l], zmS[mm][l], dot);
            float d2 = fmaxf(sqn_r + sqmS[mm] - 2.0f * dot, 0.f);
            qacc += __expf(-d2 * kscale);
        }
    }
    // reduce over 8 lanes (contiguous within warp)
#pragma unroll
    for (int o = 4; o > 0; o >>= 1) qacc += __shfl_down_sync(0xffffffffu, qacc, o, 8);
    if (j == 0) {
        int idx = b * NN + n0 + n;
        g_c[idx] = g_pi[idx] / qacc;
    }
}

// =====================================================================
// Kernel 3 (dominant): fused K-recompute + (K*c)@x + rowsum + epilogue
// Block: 256 threads handles 32 output rows x full F=256. Grid: (N/32, B).
// m tiled by 64; x tile streamed with cp.async.
// =====================================================================
struct K3Smem {
    float xs[64][256];     // 64 KB
    float zm[64][17];
    float zn[32][17];
    float w[32][65];
    float cm[64];
    float sqm[64];
    float sqn[32];
    float rsred[32][8];
    float rowscale[32];
};

__global__ void __launch_bounds__(256, 2) k_main(const float* __restrict__ x,
                                                 float* __restrict__ out,
                                                 const float* __restrict__ dtp) {
    extern __shared__ char smem_raw[];
    K3Smem& S = *reinterpret_cast<K3Smem*>(smem_raw);

    const int tid = threadIdx.x;
    const int b = blockIdx.y;
    const int n0 = blockIdx.x * 32;
    const float* xb = x + (size_t)b * NN * FF;
    const float* zb = g_z + (size_t)b * NN * LL;
    const float* sqb = g_sq + (size_t)b * NN;
    const float* cb = g_c + (size_t)b * NN;

    for (int i = tid; i < 32 * LL; i += 256) S.zn[i >> 4][i & 15] = zb[(size_t)n0 * LL + i];
    if (tid < 32) S.sqn[tid] = sqb[n0 + tid];
    __syncthreads();

    // stage-1 identity: row ns, m-group mg
    const int ns = tid & 31;
    const int mg = tid >> 5;
    float znr[LL];
#pragma unroll
    for (int l = 0; l < LL; l++) znr[l] = S.zn[ns][l];
    const float sqn_r = S.sqn[ns];
    const float kscale = 1.0f / (4.0f * EPSV);

    // stage-2 identity: f-quad fq, row-group rg (rows rg*8..rg*8+7)
    const int fq = tid & 63;
    const int rg = tid >> 6;
    float acc[8][4];
#pragma unroll
    for (int k = 0; k < 8; k++) {
#pragma unroll
        for (int c = 0; c < 4; c++) acc[k][c] = 0.f;
    }
    float rs = 0.f;

    for (int mt = 0; mt < NN / 64; mt++) {
        const int m0 = mt * 64;
        // async-fill x tile [64][256]
        {
            const float* src = xb + (size_t)m0 * FF;
            for (int i = tid; i < 64 * 64; i += 256) {
                int r = i >> 6, c = (i & 63) << 2;
                cp_async16(&S.xs[r][c], src + r * FF + c);
            }
            cp_async_commit();
        }
        // sync loads of z/c/sq tiles
        for (int i = tid; i < 64 * LL; i += 256) S.zm[i >> 4][i & 15] = zb[(size_t)m0 * LL + i];
        if (tid < 64) {
            S.cm[tid] = cb[m0 + tid];
            S.sqm[tid] = sqb[m0 + tid];
        }
        __syncthreads();

        // stage 1: w[n][m] = exp(-d2)*c[m]  (overlaps with in-flight x tile)
#pragma unroll
        for (int j = 0; j < 8; j++) {
            const int m = mg * 8 + j;
            float dot = 0.f;
#pragma unroll
            for (int l = 0; l < LL; l++) dot = fmaf(znr[l], S.zm[m][l], dot);
            float d2 = fmaxf(sqn_r + S.sqm[m] - 2.0f * dot, 0.f);
            float wv = __expf(-d2 * kscale) * S.cm[m];
            S.w[ns][m] = wv;
            rs += wv;
        }
        cp_async_wait_all();
        __syncthreads();

        // stage 2: acc += w @ x   (8 rows x 4 cols per thread)
#pragma unroll 4
        for (int m = 0; m < 64; m++) {
            float4 xv = *reinterpret_cast<const float4*>(&S.xs[m][fq << 2]);
#pragma unroll
            for (int k = 0; k < 8; k++) {
                const float wv = S.w[rg * 8 + k][m];
                acc[k][0] = fmaf(wv, xv.x, acc[k][0]);
                acc[k][1] = fmaf(wv, xv.y, acc[k][1]);
                acc[k][2] = fmaf(wv, xv.z, acc[k][2]);
                acc[k][3] = fmaf(wv, xv.w, acc[k][3]);
            }
        }
        __syncthreads();
    }

    // rowsum reduction: 8 groups per row
    S.rsred[ns][mg] = rs;
    __syncthreads();
    const float dtv = dtp[0];
    if (tid < 32) {
        float r = 1e-5f;
#pragma unroll
        for (int g = 0; g < 8; g++) r += S.rsred[tid][g];
        S.rowscale[tid] = (dtv / EPSV) / r;   // dt * 4 / row
    }
    __syncthreads();

    const float omdt = 1.0f - dtv;
    float* ob = out + (size_t)b * NN * FF;
#pragma unroll
    for (int k = 0; k < 8; k++) {
        const int r = rg * 8 + k;
        const int n = n0 + r;
        const float sc = S.rowscale[r];
        float4 xv = *reinterpret_cast<const float4*>(xb + (size_t)n * FF + (fq << 2));
        float4 o;
        o.x = omdt * xv.x + sc * acc[k][0];
        o.y = omdt * xv.y + sc * acc[k][1];
        o.z = omdt * xv.z + sc * acc[k][2];
        o.w = omdt * xv.w + sc * acc[k][3];
        *reinterpret_cast<float4*>(ob + (size_t)n * FF + (fq << 2)) = o;
    }
}

// =====================================================================
// launch
// =====================================================================
extern "C" void kernel_launch(void* const* d_in, const int* in_sizes, int n_in,
                              void* d_out, int out_size) {
    const float* x  = (const float*)d_in[0];
    const float* pw = (const float*)d_in[1];
    const float* pb = (const float*)d_in[2];
    const float* w1 = (const float*)d_in[3];
    const float* b1 = (const float*)d_in[4];
    const float* w2 = (const float*)d_in[5];
    const float* b2 = (const float*)d_in[6];
    const float* dt = (const float*)d_in[7];
    float* out = (float*)d_out;

    (void)in_sizes; (void)n_in; (void)out_size;

    const int npts = BB * NN;

    k_proj<<<npts / 16, 256>>>(x, pw, pb);
    k_pi<<<npts / 16, 256>>>(w1, b1, w2, b2);
    k_q<<<dim3(NN / 32, BB), 256>>>();

    static_assert(sizeof(K3Smem) <= 100 * 1024, "k3 smem too big");
    cudaFuncSetAttribute(k_main, cudaFuncAttributeMaxDynamicSharedMemorySize,
                         (int)sizeof(K3Smem));
    k_main<<<dim3(NN / 32, BB), 256, sizeof(K3Smem)>>>(x, out, dt);
}